// round 6
// baseline (speedup 1.0000x reference)
#include <cuda_runtime.h>
#include <math.h>

#define Bv    8
#define Tv    4096
#define Dv    1024
#define Hv    8
#define Pv    1024
#define OUTv  1024
#define NWIN  128
#define WPB   2               // windows per block
#define WG    (NWIN/WPB)      // 64 window-groups
#define TSPAN 96              // tokens spanned per block
#define NCHUNK 3              // 12 tokens per warp / 4

// ---------------- scratch (static device globals; no allocation) ----------------
__device__ __align__(16) float g_qk[Hv*Dv];             // 32 KB
__device__ __align__(16) float g_ypart[WG*Bv*Hv*Dv];    // 16 MB  [wg][b][h][d]
__device__ __align__(16) float g_y[Bv*Hv*Dv];           // 256 KB
__device__ __align__(16) float g_aggpart[32*Bv*Pv];     // 1 MB   [dseg][b][p]
__device__ __align__(16) float g_agg[Bv*Pv];            // 32 KB

// ---------------- helpers ----------------
__device__ __forceinline__ float wredsum(float v){
#pragma unroll
    for (int o = 16; o; o >>= 1) v += __shfl_xor_sync(0xffffffffu, v, o);
    return v;
}
__device__ __forceinline__ float wredmax(float v){
#pragma unroll
    for (int o = 16; o; o >>= 1) v = fmaxf(v, __shfl_xor_sync(0xffffffffu, v, o));
    return v;
}
__device__ __forceinline__ unsigned long long fma2(unsigned long long a,
                                                   unsigned long long b,
                                                   unsigned long long c){
    unsigned long long d;
    asm("fma.rn.f32x2 %0, %1, %2, %3;" : "=l"(d) : "l"(a), "l"(b), "l"(c));
    return d;
}
__device__ __forceinline__ unsigned long long add2(unsigned long long a,
                                                   unsigned long long b){
    unsigned long long d;
    asm("add.rn.f32x2 %0, %1, %2;" : "=l"(d) : "l"(a), "l"(b));
    return d;
}
__device__ __forceinline__ float2 unpack2(unsigned long long v){
    float2 r; asm("mov.b64 {%0, %1}, %2;" : "=f"(r.x), "=f"(r.y) : "l"(v)); return r;
}
__device__ __forceinline__ unsigned long long pack2(float lo, float hi){
    unsigned long long v; asm("mov.b64 %0, {%1, %2};" : "=l"(v) : "f"(lo), "f"(hi)); return v;
}
__device__ __forceinline__ unsigned long long shfl_xor64(unsigned long long v, int m){
    float2 p = unpack2(v);
    p.x = __shfl_xor_sync(0xffffffffu, p.x, m);
    p.y = __shfl_xor_sync(0xffffffffu, p.y, m);
    return pack2(p.x, p.y);
}

// one merge step of the butterfly: value k and k+n combine across lane-bit s
#define MERGE(k, n, s) {                                            \
    bool hi = (lane & (s)) != 0;                                    \
    unsigned long long keep = hi ? r[(k)+(n)] : r[(k)];             \
    unsigned long long send = hi ? r[(k)]     : r[(k)+(n)];         \
    r[(k)] = add2(keep, shfl_xor64(send, (s)));                     \
}

// ---------------- 1) qk[h,d] = sum_hd w_kv[d, h*128+hd] * query[h,hd] ----------------
__global__ void k_qk(const float* __restrict__ w_kv, const float* __restrict__ query){
    int g    = blockIdx.x * 8 + (threadIdx.x >> 5);
    int lane = threadIdx.x & 31;
    int h = g >> 10, d = g & 1023;
    float4 wv = *(const float4*)(w_kv + (size_t)d*2048 + h*128 + lane*4);
    float4 qv = *(const float4*)(query + h*128 + lane*4);
    float s = wv.x*qv.x + wv.y*qv.y + wv.z*qv.z + wv.w*qv.w;
    s = wredsum(s);
    if (lane == 0) g_qk[h*Dv + d] = s;
}

// ---------------- 2) fused logits + windowed softmax + weighted V-sum partials ----------------
// grid (wg=64, b=8), block 256 (8 warps). Block owns windows {2wg, 2wg+1},
// token span [64wg, 64wg+96). One DRAM pass over x; phase-C re-read is L2-hot.
__global__ void __launch_bounds__(256, 2) k_fused(const float* __restrict__ x){
    __shared__ float qs[Hv*Dv];                         // 32 KB
    __shared__ float lg[Hv][TSPAN+4];                   // logits (padded)
    __shared__ unsigned long long cw2[Hv][TSPAN];       // (w,w) pairs

    int tid  = threadIdx.x;
    int wg   = blockIdx.x;
    int b    = blockIdx.y;
    int tbase = wg * (32*WPB);

#pragma unroll
    for (int i = 0; i < 8; i++)
        ((float4*)qs)[tid + i*256] = ((const float4*)g_qk)[tid + i*256];
    for (int i = tid; i < Hv*TSPAN; i += 256) ((unsigned long long*)cw2)[i] = 0ull;
    __syncthreads();

    int warp = tid >> 5, lane = tid & 31;
    const float scale = 0.08838834764831845f;           // 1/sqrt(128)

    // ---- phase A: logits, 12 tokens per warp, 3 chunks of 4 ----
#pragma unroll 1
    for (int c = 0; c < NCHUNK; c++){
        int tokl = warp*(4*NCHUNK) + c*4;
        unsigned long long r[32];                       // r[h*4+j]
#pragma unroll
        for (int v = 0; v < 32; v++) r[v] = 0ull;

        const float* rp[4];
#pragma unroll
        for (int j = 0; j < 4; j++){
            int t = tbase + tokl + j;
            t = t < Tv ? t : Tv - 1;                    // clamp OOB rows (masked later)
            rp[j] = x + ((size_t)b*Tv + t)*Dv + lane*4;
        }
#pragma unroll
        for (int i = 0; i < 8; i++){
            ulonglong2 xr[4];
#pragma unroll
            for (int j = 0; j < 4; j++)
                xr[j] = *(const ulonglong2*)(rp[j] + i*128);
#pragma unroll
            for (int h = 0; h < 8; h++){
                ulonglong2 q = *(const ulonglong2*)(qs + h*Dv + i*128 + lane*4);
#pragma unroll
                for (int j = 0; j < 4; j++){
                    r[h*4+j] = fma2(xr[j].x, q.x, r[h*4+j]);
                    r[h*4+j] = fma2(xr[j].y, q.y, r[h*4+j]);
                }
            }
        }
        // static merge-butterfly: fully unrolled, compile-time indices only.
        // After all steps, lane l holds the complete sum of value l.
#pragma unroll
        for (int k = 0; k < 16; k++) MERGE(k, 16, 16);
#pragma unroll
        for (int k = 0; k < 8;  k++) MERGE(k, 8, 8);
#pragma unroll
        for (int k = 0; k < 4;  k++) MERGE(k, 4, 4);
#pragma unroll
        for (int k = 0; k < 2;  k++) MERGE(k, 2, 2);
        MERGE(0, 1, 1);

        float2 p = unpack2(r[0]);
        float sv = (p.x + p.y) * scale;
        int h = lane >> 2, j = lane & 3;
        int tok = tokl + j;
        lg[h][tok] = (tbase + tok < Tv) ? sv : -3.0e38f;
    }
    __syncthreads();

    // ---- phase B: WPB windows' softmax per head (warp == head), pair RMW ----
#pragma unroll
    for (int wi = 0; wi < WPB; wi++){
        int t0l = wi*32;
        float l0 = lg[warp][t0l + lane];
        float l1 = lg[warp][t0l + lane + 32];
        float m  = wredmax(fmaxf(l0, l1));
        float e0 = __expf(l0 - m);
        float e1 = __expf(l1 - m);
        float z  = wredsum(e0 + e1);
        float inv = (1.0f/128.0f) / z;
        float w0 = e0 * inv, w1 = e1 * inv;
        cw2[warp][t0l + lane]      = add2(cw2[warp][t0l + lane],      pack2(w0, w0));
        cw2[warp][t0l + lane + 32] = add2(cw2[warp][t0l + lane + 32], pack2(w1, w1));
    }
    __syncthreads();

    // ---- phase C: y partial, thread owns 4 d channels; x re-read hits L2 ----
    int tmax = TSPAN < (Tv - tbase) ? TSPAN : (Tv - tbase);
    const float* xb = x + ((size_t)b*Tv + tbase)*Dv + tid*4;
    unsigned long long acc[8][2];
#pragma unroll
    for (int h = 0; h < 8; h++){ acc[h][0] = 0ull; acc[h][1] = 0ull; }

#pragma unroll 4
    for (int tt = 0; tt < tmax; tt++){
        ulonglong2 xv = *(const ulonglong2*)(xb + (size_t)tt*Dv);
#pragma unroll
        for (int h = 0; h < 8; h++){
            unsigned long long w2 = cw2[h][tt];
            acc[h][0] = fma2(xv.x, w2, acc[h][0]);
            acc[h][1] = fma2(xv.y, w2, acc[h][1]);
        }
    }
    int dbase = tid*4;
#pragma unroll
    for (int h = 0; h < 8; h++){
        float2 a = unpack2(acc[h][0]);
        float2 c = unpack2(acc[h][1]);
        float4 o = make_float4(a.x, a.y, c.x, c.y);
        *(float4*)(g_ypart + ((((size_t)wg*Bv + b)*Hv + h)*Dv) + dbase) = o;
    }
}

// ---------------- 3) reduce y partials over window-groups ----------------
__global__ void k_yred(){
    int i = blockIdx.x*blockDim.x + threadIdx.x;        // 65536 = b*h*d
    float s = 0.f;
#pragma unroll
    for (int seg = 0; seg < WG; seg++) s += g_ypart[(size_t)seg*(Bv*Hv*Dv) + i];
    g_y[i] = s;
}

// ---------------- 4) agg partials: agg[b,p] = sum_d w_kv_v[d,p] * y[b, p/128, d] ----------------
// grid (dseg=32, h=8), block 256: warp = one batch, lanes = 32 float4 p's within head h
__global__ void k_agg(const float* __restrict__ w_kv){
    int tid  = threadIdx.x;
    int dseg = blockIdx.x;
    int h    = blockIdx.y;
    int p    = h*128 + (tid & 31)*4;
    int b    = tid >> 5;
    float4 acc = make_float4(0.f,0.f,0.f,0.f);
    const float* yp = g_y + ((size_t)b*Hv + h)*Dv + dseg*32;
#pragma unroll
    for (int dd = 0; dd < 32; dd++){
        int d = dseg*32 + dd;
        float4 wv = *(const float4*)(w_kv + (size_t)d*2048 + 1024 + p);
        float yv = yp[dd];
        acc.x += yv*wv.x; acc.y += yv*wv.y;
        acc.z += yv*wv.z; acc.w += yv*wv.w;
    }
    *(float4*)(g_aggpart + ((size_t)dseg*Bv + b)*Pv + p) = acc;
}

// ---------------- 5) reduce agg partials ----------------
__global__ void k_aggred(){
    int i = blockIdx.x*blockDim.x + threadIdx.x;        // 8192
    float s = 0.f;
#pragma unroll
    for (int seg = 0; seg < 32; seg++) s += g_aggpart[(size_t)seg*(Bv*Pv) + i];
    g_agg[i] = s;
}

// ---------------- 6) out[b,o] = bias[o] + sum_p w_out[o,p]*agg[b,p] ----------------
__global__ void k_out(const float* __restrict__ w_out, const float* __restrict__ w_b,
                      float* __restrict__ out){
    __shared__ float aggs[Bv*Pv];                       // 32 KB
    int tid = threadIdx.x;
#pragma unroll
    for (int i = 0; i < 8; i++)
        ((float4*)aggs)[tid + i*256] = ((const float4*)g_agg)[tid + i*256];
    __syncthreads();

    int warp = tid >> 5, lane = tid & 31;
    int o = blockIdx.x*8 + warp;
    float acc[8];
#pragma unroll
    for (int b = 0; b < 8; b++) acc[b] = 0.f;
#pragma unroll
    for (int i = 0; i < 8; i++){
        float4 w4 = *(const float4*)(w_out + (size_t)o*Pv + i*128 + lane*4);
#pragma unroll
        for (int b = 0; b < 8; b++){
            float4 a4 = *(const float4*)(aggs + b*Pv + i*128 + lane*4);
            acc[b] += w4.x*a4.x + w4.y*a4.y + w4.z*a4.z + w4.w*a4.w;
        }
    }
#pragma unroll
    for (int b = 0; b < 8; b++) acc[b] = wredsum(acc[b]);
    if (lane == 0){
        float bias = w_b[o];
#pragma unroll
        for (int b = 0; b < 8; b++) out[(size_t)b*OUTv + o] = acc[b] + bias;
    }
}

// ---------------- launch ----------------
extern "C" void kernel_launch(void* const* d_in, const int* in_sizes, int n_in,
                              void* d_out, int out_size){
    const float* x     = (const float*)d_in[0];
    const float* w_kv  = (const float*)d_in[1];
    const float* query = (const float*)d_in[2];
    const float* w_out = (const float*)d_in[3];
    const float* w_b   = (const float*)d_in[4];
    float* out = (float*)d_out;

    k_qk    <<<1024, 256>>>(w_kv, query);
    dim3 gf(WG, Bv);
    k_fused <<<gf, 256>>>(x);
    k_yred  <<<256, 256>>>();
    dim3 ga(32, 8);
    k_agg   <<<ga, 256>>>(w_kv);
    k_aggred<<<32, 256>>>();
    k_out   <<<128, 256>>>(w_out, w_b, out);
}

// round 7
// speedup vs baseline: 2.5490x; 2.5490x over previous
#include <cuda_runtime.h>
#include <math.h>

#define Bv    8
#define Tv    4096
#define Dv    1024
#define Hv    8
#define Pv    1024
#define OUTv  1024
#define NWIN  128
#define WPB   4               // windows per block
#define WG    (NWIN/WPB)      // 32 window-groups
#define TSPAN 160             // tokens spanned per block (32*WPB + 32)
#define NCHUNK 5              // 20 tokens per warp / 4

// ---------------- scratch (static device globals; no allocation) ----------------
__device__ __align__(16) float g_qk[Hv*Dv];             // 32 KB
__device__ __align__(16) float g_ypart[WG*Bv*Hv*Dv];    // 8 MB   [wg][b][h][d]
__device__ __align__(16) float g_aggpart[32*Bv*Pv];     // 1 MB   [dseg][b][p]
__device__ __align__(16) float g_agg[Bv*Pv];            // 32 KB

// ---------------- helpers ----------------
__device__ __forceinline__ float wredsum(float v){
#pragma unroll
    for (int o = 16; o; o >>= 1) v += __shfl_xor_sync(0xffffffffu, v, o);
    return v;
}
__device__ __forceinline__ float wredmax(float v){
#pragma unroll
    for (int o = 16; o; o >>= 1) v = fmaxf(v, __shfl_xor_sync(0xffffffffu, v, o));
    return v;
}
__device__ __forceinline__ unsigned long long fma2(unsigned long long a,
                                                   unsigned long long b,
                                                   unsigned long long c){
    unsigned long long d;
    asm("fma.rn.f32x2 %0, %1, %2, %3;" : "=l"(d) : "l"(a), "l"(b), "l"(c));
    return d;
}
__device__ __forceinline__ unsigned long long add2(unsigned long long a,
                                                   unsigned long long b){
    unsigned long long d;
    asm("add.rn.f32x2 %0, %1, %2;" : "=l"(d) : "l"(a), "l"(b));
    return d;
}
__device__ __forceinline__ float2 unpack2(unsigned long long v){
    float2 r; asm("mov.b64 {%0, %1}, %2;" : "=f"(r.x), "=f"(r.y) : "l"(v)); return r;
}
__device__ __forceinline__ unsigned long long pack2(float lo, float hi){
    unsigned long long v; asm("mov.b64 %0, {%1, %2};" : "=l"(v) : "f"(lo), "f"(hi)); return v;
}
__device__ __forceinline__ unsigned long long wredsum2(unsigned long long v){
#pragma unroll
    for (int o = 16; o; o >>= 1){
        unsigned long long t = __shfl_xor_sync(0xffffffffu, v, o);
        v = add2(v, t);
    }
    return v;
}

// ---------------- 1) qk[h,d] = sum_hd w_kv[d, h*128+hd] * query[h,hd] ----------------
__global__ void k_qk(const float* __restrict__ w_kv, const float* __restrict__ query){
    int g    = blockIdx.x * 8 + (threadIdx.x >> 5);
    int lane = threadIdx.x & 31;
    int h = g >> 10, d = g & 1023;
    float4 wv = *(const float4*)(w_kv + (size_t)d*2048 + h*128 + lane*4);
    float4 qv = *(const float4*)(query + h*128 + lane*4);
    float s = wv.x*qv.x + wv.y*qv.y + wv.z*qv.z + wv.w*qv.w;
    s = wredsum(s);
    if (lane == 0) g_qk[h*Dv + d] = s;
}

// ---------------- 2) fused logits + windowed softmax + weighted V-sum partials ----------------
// grid (wg=32, b=8) = 256 blocks (one full wave at 2/SM), block 256 (8 warps).
// Block owns windows [4wg, 4wg+4), token span [128wg, 128wg+160).
__global__ void __launch_bounds__(256, 2) k_fused(const float* __restrict__ x){
    __shared__ float qs[Hv*Dv];                         // 32 KB
    __shared__ float lg[Hv][TSPAN+4];                   // 5.1 KB logits (padded)
    __shared__ unsigned long long cw2[Hv][TSPAN];       // 10 KB (w,w) pairs

    int tid  = threadIdx.x;
    int wg   = blockIdx.x;
    int b    = blockIdx.y;
    int tbase = wg * (32*WPB);

#pragma unroll
    for (int i = 0; i < 8; i++)
        ((float4*)qs)[tid + i*256] = ((const float4*)g_qk)[tid + i*256];
    for (int i = tid; i < Hv*TSPAN; i += 256) ((unsigned long long*)cw2)[i] = 0ull;
    __syncthreads();

    int warp = tid >> 5, lane = tid & 31;
    const float scale = 0.08838834764831845f;           // 1/sqrt(128)

    // ---- phase A: logits, 20 tokens per warp, 5 chunks of 4 (R4-proven reduction) ----
#pragma unroll 1
    for (int c = 0; c < NCHUNK; c++){
        int tokl = warp*(4*NCHUNK) + c*4;
        unsigned long long acc[4][8];
#pragma unroll
        for (int j = 0; j < 4; j++)
#pragma unroll
            for (int h = 0; h < 8; h++) acc[j][h] = 0ull;

        const float* rp[4];
#pragma unroll
        for (int j = 0; j < 4; j++){
            int t = tbase + tokl + j;
            t = t < Tv ? t : Tv - 1;                    // clamp OOB rows (masked later)
            rp[j] = x + ((size_t)b*Tv + t)*Dv + lane*4;
        }
#pragma unroll
        for (int i = 0; i < 8; i++){
            ulonglong2 xr[4];
#pragma unroll
            for (int j = 0; j < 4; j++)
                xr[j] = *(const ulonglong2*)(rp[j] + i*128);
#pragma unroll
            for (int h = 0; h < 8; h++){
                ulonglong2 q = *(const ulonglong2*)(qs + h*Dv + i*128 + lane*4);
#pragma unroll
                for (int j = 0; j < 4; j++){
                    acc[j][h] = fma2(xr[j].x, q.x, acc[j][h]);
                    acc[j][h] = fma2(xr[j].y, q.y, acc[j][h]);
                }
            }
        }
        float my = 0.f;
#pragma unroll
        for (int h = 0; h < 8; h++)
#pragma unroll
            for (int j = 0; j < 4; j++){
                unsigned long long r = wredsum2(acc[j][h]);
                float2 p = unpack2(r);
                float s = (p.x + p.y) * scale;
                if (lane == h*4 + j) my = s;
            }
        int h = lane >> 2, j = lane & 3;
        int tok = tokl + j;
        lg[h][tok] = (tbase + tok < Tv) ? my : -3.0e38f;
    }
    __syncthreads();

    // ---- phase B: WPB windows' softmax per head (warp == head), pair RMW ----
#pragma unroll
    for (int wi = 0; wi < WPB; wi++){
        int t0l = wi*32;
        float l0 = lg[warp][t0l + lane];
        float l1 = lg[warp][t0l + lane + 32];
        float m  = wredmax(fmaxf(l0, l1));
        float e0 = __expf(l0 - m);
        float e1 = __expf(l1 - m);
        float z  = wredsum(e0 + e1);
        float inv = (1.0f/128.0f) / z;
        float w0 = e0 * inv, w1 = e1 * inv;
        cw2[warp][t0l + lane]      = add2(cw2[warp][t0l + lane],      pack2(w0, w0));
        cw2[warp][t0l + lane + 32] = add2(cw2[warp][t0l + lane + 32], pack2(w1, w1));
    }
    __syncthreads();

    // ---- phase C: y partial, thread owns 4 d channels; x re-read hits L2 ----
    int tmax = TSPAN < (Tv - tbase) ? TSPAN : (Tv - tbase);
    const float* xb = x + ((size_t)b*Tv + tbase)*Dv + tid*4;
    unsigned long long acc[8][2];
#pragma unroll
    for (int h = 0; h < 8; h++){ acc[h][0] = 0ull; acc[h][1] = 0ull; }

#pragma unroll 4
    for (int tt = 0; tt < tmax; tt++){
        ulonglong2 xv = *(const ulonglong2*)(xb + (size_t)tt*Dv);
#pragma unroll
        for (int h = 0; h < 8; h++){
            unsigned long long w2 = cw2[h][tt];
            acc[h][0] = fma2(xv.x, w2, acc[h][0]);
            acc[h][1] = fma2(xv.y, w2, acc[h][1]);
        }
    }
    int dbase = tid*4;
#pragma unroll
    for (int h = 0; h < 8; h++){
        float2 a = unpack2(acc[h][0]);
        float2 c = unpack2(acc[h][1]);
        float4 o = make_float4(a.x, a.y, c.x, c.y);
        *(float4*)(g_ypart + ((((size_t)wg*Bv + b)*Hv + h)*Dv) + dbase) = o;
    }
}

// ---------------- 3) fused y-reduce + agg partials ----------------
// grid (dseg=32, h=8) = 256 blocks, block 256 (warp = batch b, lanes = d/p).
// Step 1: lane dd reduces y[b,h,dseg*32+dd] over 32 wg partials.
// Step 2: loop dd, broadcast y via shfl, FMA against w_kv V-column float4.
__global__ void k_agg(const float* __restrict__ w_kv){
    int tid  = threadIdx.x;
    int dseg = blockIdx.x;
    int h    = blockIdx.y;
    int b    = tid >> 5, lane = tid & 31;

    // reduce ypart over window-groups for this (b,h,dseg*32+lane)
    const float* yp = g_ypart + (((size_t)b*Hv + h)*Dv) + dseg*32 + lane;
    float yv = 0.f;
#pragma unroll 8
    for (int wgi = 0; wgi < WG; wgi++)
        yv += yp[(size_t)wgi*(Bv*Hv*Dv)];

    int p = h*128 + lane*4;
    float4 acc = make_float4(0.f,0.f,0.f,0.f);
#pragma unroll
    for (int dd = 0; dd < 32; dd++){
        float yd = __shfl_sync(0xffffffffu, yv, dd);
        int d = dseg*32 + dd;
        float4 wv = *(const float4*)(w_kv + (size_t)d*2048 + 1024 + p);
        acc.x += yd*wv.x; acc.y += yd*wv.y;
        acc.z += yd*wv.z; acc.w += yd*wv.w;
    }
    *(float4*)(g_aggpart + ((size_t)dseg*Bv + b)*Pv + p) = acc;
}

// ---------------- 4) reduce agg partials ----------------
__global__ void k_aggred(){
    int i = blockIdx.x*blockDim.x + threadIdx.x;        // 8192
    float s = 0.f;
#pragma unroll
    for (int seg = 0; seg < 32; seg++) s += g_aggpart[(size_t)seg*(Bv*Pv) + i];
    g_agg[i] = s;
}

// ---------------- 5) out[b,o] = bias[o] + sum_p w_out[o,p]*agg[b,p] ----------------
__global__ void k_out(const float* __restrict__ w_out, const float* __restrict__ w_b,
                      float* __restrict__ out){
    __shared__ float aggs[Bv*Pv];                       // 32 KB
    int tid = threadIdx.x;
#pragma unroll
    for (int i = 0; i < 8; i++)
        ((float4*)aggs)[tid + i*256] = ((const float4*)g_agg)[tid + i*256];
    __syncthreads();

    int warp = tid >> 5, lane = tid & 31;
    int o = blockIdx.x*8 + warp;
    float acc[8];
#pragma unroll
    for (int b = 0; b < 8; b++) acc[b] = 0.f;
#pragma unroll
    for (int i = 0; i < 8; i++){
        float4 w4 = *(const float4*)(w_out + (size_t)o*Pv + i*128 + lane*4);
#pragma unroll
        for (int b = 0; b < 8; b++){
            float4 a4 = *(const float4*)(aggs + b*Pv + i*128 + lane*4);
            acc[b] += w4.x*a4.x + w4.y*a4.y + w4.z*a4.z + w4.w*a4.w;
        }
    }
#pragma unroll
    for (int b = 0; b < 8; b++) acc[b] = wredsum(acc[b]);
    if (lane == 0){
        float bias = w_b[o];
#pragma unroll
        for (int b = 0; b < 8; b++) out[(size_t)b*OUTv + o] = acc[b] + bias;
    }
}

// ---------------- launch ----------------
extern "C" void kernel_launch(void* const* d_in, const int* in_sizes, int n_in,
                              void* d_out, int out_size){
    const float* x     = (const float*)d_in[0];
    const float* w_kv  = (const float*)d_in[1];
    const float* query = (const float*)d_in[2];
    const float* w_out = (const float*)d_in[3];
    const float* w_b   = (const float*)d_in[4];
    float* out = (float*)d_out;

    k_qk    <<<1024, 256>>>(w_kv, query);
    dim3 gf(WG, Bv);
    k_fused <<<gf, 256>>>(x);
    dim3 ga(32, 8);
    k_agg   <<<ga, 256>>>(w_kv);
    k_aggred<<<32, 256>>>();
    k_out   <<<128, 256>>>(w_out, w_b, out);
}